// round 5
// baseline (speedup 1.0000x reference)
#include <cuda_runtime.h>
#include <cuda_bf16.h>
#include <stdint.h>

// PyramidROIAlign: output [B,N,7,7,256] f32, levels p2..p5 (256/128/64/32), NHWC.
// R5: two kernels.
//  1) precompute: one thread per (roi,py) writes a 32B record
//     {fmap ptr, rowT, rowB, ly, xsc, xst, W-1} -> __device__ scratch.
//  2) main: one WARP per (roi,py,px) sample (R3 shape, occ ~83%), but all the
//     expensive per-sample setup (box load, sqrt/log2, level select, y math)
//     is replaced by 2 uniform LDG.128 of the record. Lanes do 8x LDG.128 +
//     FFMA + 2x STG.128 (streaming).

#define POOLX 7
#define C4N 64   // 256 ch / 4
#define MAX_ROIS 8192

// 2 float4 per (roi,py) record
__device__ float4 g_recs[MAX_ROIS * POOLX * 2];

__global__ __launch_bounds__(256) void roi_setup_kernel(
    const float* __restrict__ boxes,   // [M,4]
    const float* __restrict__ meta,    // [B,93]
    const float* __restrict__ p2,
    const float* __restrict__ p3,
    const float* __restrict__ p4,
    const float* __restrict__ p5,
    int M7, int N)
{
    int tid = blockIdx.x * blockDim.x + threadIdx.x;
    if (tid >= M7) return;
    int py  = tid % POOLX;
    int roi = tid / POOLX;
    int b   = roi / N;

    float4 bx = __ldg(((const float4*)boxes) + roi);
    float y1 = bx.x, x1 = bx.y, y2 = bx.z, x2 = bx.w;
    float h = y2 - y1, w = x2 - x1;

    float area  = __ldg(meta + 4) * __ldg(meta + 5);
    float scale = sqrtf(fmaxf(h * w, 1e-12f));
    float rl    = log2f(scale * sqrtf(area) / 224.0f);
    int lvl = 4 + (int)rintf(rl);
    lvl = min(max(lvl, 2), 5);

    const float* fmap;
    int H;
    if      (lvl == 2) { fmap = p2; H = 256; }
    else if (lvl == 3) { fmap = p3; H = 128; }
    else if (lvl == 4) { fmap = p4; H = 64;  }
    else               { fmap = p5; H = 32;  }
    const int W = H;

    float ty = (float)py * (1.0f / 6.0f);
    float ys = (y1 + ty * h) * (float)(H - 1);
    float fy = floorf(ys);
    float ly = ys - fy;
    int y0  = min(max((int)fy,     0), H - 1);
    int y1i = min(max((int)fy + 1, 0), H - 1);

    int rowT = (b * H + y0 ) * W;
    int rowB = (b * H + y1i) * W;

    float xsc = x1 * (float)(W - 1);
    float xst = w * (float)(W - 1) * (1.0f / 6.0f);

    uint64_t pv = (uint64_t)fmap;
    float4 r0, r1;
    r0.x = __uint_as_float((uint32_t)(pv & 0xFFFFFFFFu));
    r0.y = __uint_as_float((uint32_t)(pv >> 32));
    r0.z = __int_as_float(rowT);
    r0.w = __int_as_float(rowB);
    r1.x = ly;
    r1.y = xsc;
    r1.z = xst;
    r1.w = __int_as_float(W - 1);

    g_recs[tid * 2]     = r0;
    g_recs[tid * 2 + 1] = r1;
}

__global__ __launch_bounds__(256, 8) void roi_align_main_kernel(
    float* __restrict__ out,
    int totalWarps)
{
    int gw   = (blockIdx.x * blockDim.x + threadIdx.x) >> 5;  // sample = roi*49+pos
    int lane = threadIdx.x & 31;
    if (gw >= totalWarps) return;

    int s7 = gw / 7;            // = roi*7 + py   (record index)
    int px = gw - s7 * 7;

    float4 r0 = __ldg(&g_recs[s7 * 2]);
    float4 r1 = __ldg(&g_recs[s7 * 2 + 1]);

    uint64_t pv = (uint64_t)__float_as_uint(r0.x)
                | ((uint64_t)__float_as_uint(r0.y) << 32);
    const float4* f4 = (const float4*)pv;
    int   rowT = __float_as_int(r0.z);
    int   rowB = __float_as_int(r0.w);
    float ly   = r1.x;
    float xsc  = r1.y;
    float xst  = r1.z;
    int   Wm1  = __float_as_int(r1.w);

    float xs = fmaf((float)px, xst, xsc);
    float fx = floorf(xs);
    float lx = xs - fx;
    int x0  = min(max((int)fx,     0), Wm1);
    int x1i = min(max((int)fx + 1, 0), Wm1);

    float w11 = ly * lx;
    float w01 = lx - w11;            // lx*(1-ly)
    float w10 = ly - w11;            // ly*(1-lx)
    float w00 = 1.0f - lx - w10;     // (1-lx)*(1-ly)

    int o00 = (rowT + x0 ) * C4N + lane;
    int o01 = (rowT + x1i) * C4N + lane;
    int o10 = (rowB + x0 ) * C4N + lane;
    int o11 = (rowB + x1i) * C4N + lane;

    float4 a00 = __ldg(f4 + o00);
    float4 a01 = __ldg(f4 + o01);
    float4 a10 = __ldg(f4 + o10);
    float4 a11 = __ldg(f4 + o11);
    float4 b00 = __ldg(f4 + o00 + 32);
    float4 b01 = __ldg(f4 + o01 + 32);
    float4 b10 = __ldg(f4 + o10 + 32);
    float4 b11 = __ldg(f4 + o11 + 32);

    float4 ra, rb;
    ra.x = a00.x*w00 + a01.x*w01 + a10.x*w10 + a11.x*w11;
    ra.y = a00.y*w00 + a01.y*w01 + a10.y*w10 + a11.y*w11;
    ra.z = a00.z*w00 + a01.z*w01 + a10.z*w10 + a11.z*w11;
    ra.w = a00.w*w00 + a01.w*w01 + a10.w*w10 + a11.w*w11;
    rb.x = b00.x*w00 + b01.x*w01 + b10.x*w10 + b11.x*w11;
    rb.y = b00.y*w00 + b01.y*w01 + b10.y*w10 + b11.y*w11;
    rb.z = b00.z*w00 + b01.z*w01 + b10.z*w10 + b11.z*w11;
    rb.w = b00.w*w00 + b01.w*w01 + b10.w*w10 + b11.w*w11;

    float4* o4 = (float4*)out + gw * C4N;
    __stcs(o4 + lane,      ra);
    __stcs(o4 + lane + 32, rb);
}

extern "C" void kernel_launch(void* const* d_in, const int* in_sizes, int n_in,
                              void* d_out, int out_size) {
    const float* boxes = (const float*)d_in[0];
    const float* meta  = (const float*)d_in[1];
    const float* p2    = (const float*)d_in[2];
    const float* p3    = (const float*)d_in[3];
    const float* p4    = (const float*)d_in[4];
    const float* p5    = (const float*)d_in[5];
    float* out = (float*)d_out;

    int B = in_sizes[1] / 93;              // image_meta [B,93]
    if (B <= 0) B = 2;
    int N = in_sizes[0] / (4 * B);         // boxes [B,N,4]
    int M = B * N;
    if (M > MAX_ROIS) M = MAX_ROIS;        // scratch cap (dataset: M=2000)
    int M7 = M * POOLX;

    roi_setup_kernel<<<(M7 + 255) / 256, 256>>>(boxes, meta, p2, p3, p4, p5, M7, N);

    int totalWarps = M * 49;               // one warp per (roi, py, px)
    int warpsPerBlock = 256 / 32;
    int blocks = (totalWarps + warpsPerBlock - 1) / warpsPerBlock;
    roi_align_main_kernel<<<blocks, 256>>>(out, totalWarps);
}